// round 6
// baseline (speedup 1.0000x reference)
#include <cuda_runtime.h>
#include <math.h>

#define SS 512
#define BB 128
#define HH 1024
#define G4 4096
#define NBLK 128

// ---------------- static device scratch (no runtime allocation) ------------------
__device__ float g_Wcat[(size_t)G4 * HH];   // interleaved combined weights (t>=1)
__device__ float g_W0cat[(size_t)G4 * HH];  // interleaved step-0 weights (x=0)
__device__ float g_bc[G4];                  // interleaved combined biases
__device__ float g_h0[BB * HH];             // initial hidden state
__device__ float g_hist[(size_t)BB * SS * HH]; // h_t history [b][t][h]
__device__ float g_ec[BB * SS * 2];         // enc projected through Wp ctx rows [b][s][2]
__device__ unsigned g_arr;                  // grid-barrier arrive counter
__device__ unsigned g_rel;                  // grid-barrier release generation

// ---------------- f32x2 packed helpers -------------------------------------------
__device__ __forceinline__ unsigned long long pk2(float x) {
    unsigned long long r;
    asm("mov.b64 %0, {%1, %1};" : "=l"(r) : "f"(x));
    return r;
}
__device__ __forceinline__ void fma2(unsigned long long& d,
                                     unsigned long long a, unsigned long long b) {
    asm("fma.rn.f32x2 %0, %1, %2, %0;" : "+l"(d) : "l"(a), "l"(b));
}
__device__ __forceinline__ void unp(unsigned long long v, float& a, float& b) {
    asm("mov.b64 {%0, %1}, %2;" : "=f"(a), "=f"(b) : "l"(v));
}

// ---------------- prep: interleaved weights/biases, h0, barrier reset ------------
// interleaved col n = u*4 + g, gate g in {0:r, 1:z, 2:xn, 3:hn}
__global__ void prep_kernel(const float* __restrict__ Wih, const float* __restrict__ Whh,
                            const float* __restrict__ bih, const float* __restrict__ bhh,
                            const float* __restrict__ last) {
    const size_t total = (size_t)G4 * HH;
    const size_t tid0 = (size_t)blockIdx.x * blockDim.x + threadIdx.x;
    if (tid0 == 0) { g_arr = 0u; g_rel = 0u; }
    for (size_t idx = tid0; idx < total; idx += (size_t)gridDim.x * blockDim.x) {
        const int n = (int)(idx >> 10), k = (int)(idx & 1023);
        const int u = n >> 2, g = n & 3;
        float wc, w0;
        if (g == 0)      { float a = Wih[(size_t)u * HH + k],            b = Whh[(size_t)u * HH + k];            wc = a + b; w0 = b; }
        else if (g == 1) { float a = Wih[(size_t)(HH + u) * HH + k],     b = Whh[(size_t)(HH + u) * HH + k];     wc = a + b; w0 = b; }
        else if (g == 2) { wc = Wih[(size_t)(2 * HH + u) * HH + k];      w0 = 0.f; }
        else             { float b = Whh[(size_t)(2 * HH + u) * HH + k]; wc = b;    w0 = b; }
        g_Wcat[idx] = wc;
        g_W0cat[idx] = w0;
        if (k == 0) {
            float bc;
            if (g == 0)      bc = bih[u] + bhh[u];
            else if (g == 1) bc = bih[HH + u] + bhh[HH + u];
            else if (g == 2) bc = bih[2 * HH + u];
            else             bc = bhh[2 * HH + u];
            g_bc[n] = bc;
        }
        if (idx < (size_t)BB * HH) g_h0[idx] = last[idx];
    }
}

// ---------------- ec: g_ec[b][s][j] = Wp[j,:1024] . enc[s][b][:] -----------------
__global__ void __launch_bounds__(256) ec_kernel(const float* __restrict__ enc,
                                                 const float* __restrict__ Wp) {
    const int gw = (blockIdx.x * 256 + threadIdx.x) >> 5;   // 0..2047
    const int l = threadIdx.x & 31;
    for (int rr = 0; rr < 32; rr++) {
        const int row = gw * 32 + rr;                        // = s*BB + b
        const int s = row >> 7, b = row & 127;
        const float* e = enc + (size_t)row * HH;
        float p0 = 0.f, p1 = 0.f;
#pragma unroll
        for (int c = 0; c < 8; c++) {
            float4 v  = *(const float4*)(e + l * 4 + c * 128);
            float4 w0 = *(const float4*)(Wp + l * 4 + c * 128);
            float4 w1 = *(const float4*)(Wp + 2048 + l * 4 + c * 128);
            p0 += v.x * w0.x + v.y * w0.y + v.z * w0.z + v.w * w0.w;
            p1 += v.x * w1.x + v.y * w1.y + v.z * w1.z + v.w * w1.w;
        }
#pragma unroll
        for (int o = 16; o; o >>= 1) {
            p0 += __shfl_xor_sync(~0u, p0, o);
            p1 += __shfl_xor_sync(~0u, p1, o);
        }
        if (l == 0) {
            g_ec[((size_t)b * SS + s) * 2 + 0] = p0;
            g_ec[((size_t)b * SS + s) * 2 + 1] = p1;
        }
    }
}

// ---------------- persistent recurrence: 512 steps, 1 grid barrier each ----------
// 128 blocks = 4 m-tiles (batch 32) x 32 n-tiles (128 interleaved gate cols = 32 units).
// Thread tile 4m x 4n, f32x2 packed FMA on n-pairs. Gate fusion is block-local.
__global__ void __launch_bounds__(256, 1) rec_kernel() {
    __shared__ float As[16][36];
    __shared__ float Bs[16][132];
    const int tid = threadIdx.x;
    const int blk = blockIdx.x;
    const int m0 = (blk >> 5) * 32;
    const int n0 = (blk & 31) * 128;
    const int ty = tid >> 5, tx = tid & 31;
    const int am = tid >> 3, ak = (tid & 7) << 1;
    const int bn = tid >> 1, bk = (tid & 1) << 3;
    unsigned gen = 0;

    for (int t = 0; t < SS; t++) {
        const float* W = (t == 0) ? g_W0cat : g_Wcat;
        const float* arow = (t == 0) ? (g_h0 + (size_t)(m0 + am) * HH)
                                     : (g_hist + ((size_t)(m0 + am) * SS + (t - 1)) * HH);
        const float* brow = W + (size_t)(n0 + bn) * HH + bk;

        unsigned long long acc[4][2];
#pragma unroll
        for (int i = 0; i < 4; i++) { acc[i][0] = 0ull; acc[i][1] = 0ull; }

        for (int c = 0; c < 64; c++) {
            __syncthreads();
            float2 a2 = *(const float2*)(arow + c * 16 + ak);
            As[ak][am] = a2.x; As[ak + 1][am] = a2.y;
            float4 w4a = *(const float4*)(brow + c * 16);
            float4 w4b = *(const float4*)(brow + c * 16 + 4);
            Bs[bk + 0][bn] = w4a.x; Bs[bk + 1][bn] = w4a.y;
            Bs[bk + 2][bn] = w4a.z; Bs[bk + 3][bn] = w4a.w;
            Bs[bk + 4][bn] = w4b.x; Bs[bk + 5][bn] = w4b.y;
            Bs[bk + 6][bn] = w4b.z; Bs[bk + 7][bn] = w4b.w;
            __syncthreads();
#pragma unroll
            for (int k = 0; k < 16; k++) {
                float4 av = *(const float4*)&As[k][ty * 4];
                ulonglong2 bp = *(const ulonglong2*)&Bs[k][tx * 4];
                unsigned long long ax = pk2(av.x), ay = pk2(av.y);
                unsigned long long az = pk2(av.z), aw = pk2(av.w);
                fma2(acc[0][0], ax, bp.x); fma2(acc[0][1], ax, bp.y);
                fma2(acc[1][0], ay, bp.x); fma2(acc[1][1], ay, bp.y);
                fma2(acc[2][0], az, bp.x); fma2(acc[2][1], az, bp.y);
                fma2(acc[3][0], aw, bp.x); fma2(acc[3][1], aw, bp.y);
            }
        }

        // gate fusion: this thread owns unit u for 4 batch rows
        const int u = (n0 >> 2) + tx;
        float4 bv = *(const float4*)&g_bc[u * 4];
#pragma unroll
        for (int i = 0; i < 4; i++) {
            const int b = m0 + ty * 4 + i;
            float pr, pz, pxn, phn;
            unp(acc[i][0], pr, pz);
            unp(acc[i][1], pxn, phn);
            float hp = (t == 0) ? g_h0[(size_t)b * HH + u]
                                : g_hist[((size_t)b * SS + (t - 1)) * HH + u];
            float r = 1.f / (1.f + expf(-(pr + bv.x)));
            float z = 1.f / (1.f + expf(-(pz + bv.y)));
            float nn = tanhf(pxn + bv.z + r * (phn + bv.w));
            g_hist[((size_t)b * SS + t) * HH + u] = (1.f - z) * nn + z * hp;
        }

        // grid barrier (all 128 blocks co-resident)
        __syncthreads();
        if (tid == 0) {
            gen++;
            __threadfence();
            unsigned prev = atomicAdd(&g_arr, 1u);
            if (prev == NBLK - 1) {
                g_arr = 0u;
                __threadfence();
                atomicExch(&g_rel, gen);
            } else {
                while (*(volatile unsigned*)&g_rel < gen) {}
                __threadfence();
            }
        }
        __syncthreads();
    }
}

// ---------------- batched attention + output -------------------------------------
// 1024 blocks = 128 b x 8 t-tiles(64). Online softmax over s (length-masked),
// accumulating only the 2 projected scalars per (b,t).
__global__ void __launch_bounds__(256) att_kernel(const float* __restrict__ enc,
                                                  const float* __restrict__ Wp,
                                                  const float* __restrict__ bp,
                                                  const int* __restrict__ lens,
                                                  float* __restrict__ out) {
    __shared__ float As[16][68];
    __shared__ float Bs[16][68];
    __shared__ float ec_s[64][2];
    const int bb = blockIdx.x >> 3;
    const int t0 = (blockIdx.x & 7) << 6;
    const int tid = threadIdx.x;
    const int ty = tid >> 4, tx = tid & 15;
    const int len = lens[bb];

    // hidden-state part of the projection: ph[j] = Wp[j,1024:] . h_t
    float ph0[4], ph1[4];
#pragma unroll
    for (int i = 0; i < 4; i++) {
        const int t = t0 + ty * 4 + i;
        const float* h = g_hist + ((size_t)bb * SS + t) * HH + tx * 64;
        float s0 = 0.f, s1 = 0.f;
#pragma unroll
        for (int c = 0; c < 16; c++) {
            float4 hv = *(const float4*)(h + c * 4);
            float4 w0 = *(const float4*)(Wp + 1024 + tx * 64 + c * 4);
            float4 w1 = *(const float4*)(Wp + 3072 + tx * 64 + c * 4);
            s0 += hv.x * w0.x + hv.y * w0.y + hv.z * w0.z + hv.w * w0.w;
            s1 += hv.x * w1.x + hv.y * w1.y + hv.z * w1.z + hv.w * w1.w;
        }
#pragma unroll
        for (int o = 8; o; o >>= 1) {
            s0 += __shfl_xor_sync(~0u, s0, o);
            s1 += __shfl_xor_sync(~0u, s1, o);
        }
        ph0[i] = s0; ph1[i] = s1;
    }

    float m[4], l[4], a0[4], a1[4];
#pragma unroll
    for (int i = 0; i < 4; i++) { m[i] = -1e30f; l[i] = 0.f; a0[i] = 0.f; a1[i] = 0.f; }

    const int am = tid >> 2, ak4 = (tid & 3) << 2;
    const float* hrow = g_hist + ((size_t)bb * SS + t0 + am) * HH + ak4;

    for (int sbase = 0; sbase < len; sbase += 64) {
        __syncthreads();
        if (tid < 64) {
            float2 e = *(const float2*)&g_ec[((size_t)bb * SS + sbase + tid) * 2];
            ec_s[tid][0] = e.x; ec_s[tid][1] = e.y;
        }
        const float* erow = enc + ((size_t)(sbase + am) * BB + bb) * HH + ak4;
        unsigned long long sc[4][2];
#pragma unroll
        for (int i = 0; i < 4; i++) { sc[i][0] = 0ull; sc[i][1] = 0ull; }

        for (int c = 0; c < 64; c++) {
            __syncthreads();
            float4 a4 = *(const float4*)(hrow + c * 16);
            As[ak4 + 0][am] = a4.x; As[ak4 + 1][am] = a4.y;
            As[ak4 + 2][am] = a4.z; As[ak4 + 3][am] = a4.w;
            float4 b4 = *(const float4*)(erow + c * 16);
            Bs[ak4 + 0][am] = b4.x; Bs[ak4 + 1][am] = b4.y;
            Bs[ak4 + 2][am] = b4.z; Bs[ak4 + 3][am] = b4.w;
            __syncthreads();
#pragma unroll
            for (int k = 0; k < 16; k++) {
                float4 av = *(const float4*)&As[k][ty * 4];
                ulonglong2 bpv = *(const ulonglong2*)&Bs[k][tx * 4];
                unsigned long long ax = pk2(av.x), ay = pk2(av.y);
                unsigned long long az = pk2(av.z), aw = pk2(av.w);
                fma2(sc[0][0], ax, bpv.x); fma2(sc[0][1], ax, bpv.y);
                fma2(sc[1][0], ay, bpv.x); fma2(sc[1][1], ay, bpv.y);
                fma2(sc[2][0], az, bpv.x); fma2(sc[2][1], az, bpv.y);
                fma2(sc[3][0], aw, bpv.x); fma2(sc[3][1], aw, bpv.y);
            }
        }

#pragma unroll
        for (int i = 0; i < 4; i++) {
            float s4[4];
            unp(sc[i][0], s4[0], s4[1]);
            unp(sc[i][1], s4[2], s4[3]);
#pragma unroll
            for (int j = 0; j < 4; j++)
                if (sbase + tx * 4 + j >= len) s4[j] = -1e30f;
            float cm = fmaxf(fmaxf(s4[0], s4[1]), fmaxf(s4[2], s4[3]));
#pragma unroll
            for (int o = 8; o; o >>= 1) cm = fmaxf(cm, __shfl_xor_sync(~0u, cm, o));
            const float mn = fmaxf(m[i], cm);
            const float alpha = __expf(m[i] - mn);
            float ws = 0.f, w0 = 0.f, w1 = 0.f;
#pragma unroll
            for (int j = 0; j < 4; j++) {
                float w = __expf(s4[j] - mn);
                ws += w;
                w0 += w * ec_s[tx * 4 + j][0];
                w1 += w * ec_s[tx * 4 + j][1];
            }
#pragma unroll
            for (int o = 8; o; o >>= 1) {
                ws += __shfl_xor_sync(~0u, ws, o);
                w0 += __shfl_xor_sync(~0u, w0, o);
                w1 += __shfl_xor_sync(~0u, w1, o);
            }
            l[i] = l[i] * alpha + ws;
            a0[i] = a0[i] * alpha + w0;
            a1[i] = a1[i] * alpha + w1;
            m[i] = mn;
        }
    }

    if (tx == 0) {
#pragma unroll
        for (int i = 0; i < 4; i++) {
            const int t = t0 + ty * 4 + i;
            const float inv = 1.f / l[i];
            out[((size_t)bb * SS + t) * 2 + 0] = a0[i] * inv + ph0[i] + bp[0];
            out[((size_t)bb * SS + t) * 2 + 1] = a1[i] * inv + ph1[i] + bp[1];
        }
    }
}

extern "C" void kernel_launch(void* const* d_in, const int* in_sizes, int n_in,
                              void* d_out, int out_size) {
    const float* enc  = (const float*)d_in[0];
    const float* last = (const float*)d_in[1];
    const float* Wih  = (const float*)d_in[2];
    const float* Whh  = (const float*)d_in[3];
    const float* bih  = (const float*)d_in[4];
    const float* bhh  = (const float*)d_in[5];
    const float* Wp   = (const float*)d_in[6];
    const float* bp   = (const float*)d_in[7];
    const int*   lens = (const int*)d_in[8];
    float* out = (float*)d_out;

    prep_kernel<<<4096, 256>>>(Wih, Whh, bih, bhh, last);
    ec_kernel<<<256, 256>>>(enc, Wp);
    rec_kernel<<<NBLK, 256>>>();
    att_kernel<<<1024, 256>>>(enc, Wp, bp, lens, out);
}

// round 7
// speedup vs baseline: 1.5152x; 1.5152x over previous
#include <cuda_runtime.h>
#include <math.h>

#define SS 512
#define BB 128
#define HH 1024
#define G4 4096
#define NBLK 128

// ---------------- static device scratch (no runtime allocation) ------------------
__device__ float g_Wcat[(size_t)G4 * HH];   // interleaved combined weights (t>=1)
__device__ float g_W0cat[(size_t)G4 * HH];  // interleaved step-0 weights (x=0)
__device__ float g_bc[G4];                  // interleaved combined biases
__device__ float g_h0[BB * HH];             // initial hidden state
__device__ float g_hist[(size_t)BB * SS * HH]; // h_t history [b][t][h]
__device__ float g_ec[BB * SS * 2];         // enc projected through Wp ctx rows [b][s][2]
__device__ unsigned g_arr;                  // grid-barrier arrive counter
__device__ unsigned g_rel;                  // grid-barrier release generation

// ---------------- f32x2 packed helpers -------------------------------------------
__device__ __forceinline__ unsigned long long pk2(float x) {
    unsigned long long r;
    asm("mov.b64 %0, {%1, %1};" : "=l"(r) : "f"(x));
    return r;
}
__device__ __forceinline__ void fma2(unsigned long long& d,
                                     unsigned long long a, unsigned long long b) {
    asm("fma.rn.f32x2 %0, %1, %2, %0;" : "+l"(d) : "l"(a), "l"(b));
}
__device__ __forceinline__ void unp(unsigned long long v, float& a, float& b) {
    asm("mov.b64 {%0, %1}, %2;" : "=f"(a), "=f"(b) : "l"(v));
}

// ---------------- prep: interleaved weights/biases, h0, barrier reset ------------
// interleaved col n = u*4 + g, gate g in {0:r, 1:z, 2:xn, 3:hn}
__global__ void prep_kernel(const float* __restrict__ Wih, const float* __restrict__ Whh,
                            const float* __restrict__ bih, const float* __restrict__ bhh,
                            const float* __restrict__ last) {
    const size_t total = (size_t)G4 * HH;
    const size_t tid0 = (size_t)blockIdx.x * blockDim.x + threadIdx.x;
    if (tid0 == 0) { g_arr = 0u; g_rel = 0u; }
    for (size_t idx = tid0; idx < total; idx += (size_t)gridDim.x * blockDim.x) {
        const int n = (int)(idx >> 10), k = (int)(idx & 1023);
        const int u = n >> 2, g = n & 3;
        float wc, w0;
        if (g == 0)      { float a = Wih[(size_t)u * HH + k],            b = Whh[(size_t)u * HH + k];            wc = a + b; w0 = b; }
        else if (g == 1) { float a = Wih[(size_t)(HH + u) * HH + k],     b = Whh[(size_t)(HH + u) * HH + k];     wc = a + b; w0 = b; }
        else if (g == 2) { wc = Wih[(size_t)(2 * HH + u) * HH + k];      w0 = 0.f; }
        else             { float b = Whh[(size_t)(2 * HH + u) * HH + k]; wc = b;    w0 = b; }
        g_Wcat[idx] = wc;
        g_W0cat[idx] = w0;
        if (k == 0) {
            float bc;
            if (g == 0)      bc = bih[u] + bhh[u];
            else if (g == 1) bc = bih[HH + u] + bhh[HH + u];
            else if (g == 2) bc = bih[2 * HH + u];
            else             bc = bhh[2 * HH + u];
            g_bc[n] = bc;
        }
        if (idx < (size_t)BB * HH) g_h0[idx] = last[idx];
    }
}

// ---------------- ec: g_ec[b][s][j] = Wp[j,:1024] . enc[s][b][:] -----------------
__global__ void __launch_bounds__(256) ec_kernel(const float* __restrict__ enc,
                                                 const float* __restrict__ Wp) {
    const int gw = (blockIdx.x * 256 + threadIdx.x) >> 5;   // 0..2047
    const int l = threadIdx.x & 31;
    for (int rr = 0; rr < 32; rr++) {
        const int row = gw * 32 + rr;                        // = s*BB + b
        const int s = row >> 7, b = row & 127;
        const float* e = enc + (size_t)row * HH;
        float p0 = 0.f, p1 = 0.f;
#pragma unroll
        for (int c = 0; c < 8; c++) {
            float4 v  = *(const float4*)(e + l * 4 + c * 128);
            float4 w0 = *(const float4*)(Wp + l * 4 + c * 128);
            float4 w1 = *(const float4*)(Wp + 2048 + l * 4 + c * 128);
            p0 += v.x * w0.x + v.y * w0.y + v.z * w0.z + v.w * w0.w;
            p1 += v.x * w1.x + v.y * w1.y + v.z * w1.z + v.w * w1.w;
        }
#pragma unroll
        for (int o = 16; o; o >>= 1) {
            p0 += __shfl_xor_sync(~0u, p0, o);
            p1 += __shfl_xor_sync(~0u, p1, o);
        }
        if (l == 0) {
            g_ec[((size_t)b * SS + s) * 2 + 0] = p0;
            g_ec[((size_t)b * SS + s) * 2 + 1] = p1;
        }
    }
}

// ---------------- persistent recurrence: 512 steps, 1 grid barrier each ----------
// 128 blocks = 4 m-tiles (batch 32) x 32 n-tiles (128 interleaved gate cols).
// 128 threads, thread tile 8m x 4n (2 f32x2 pairs). Double-buffered smem with
// register prefetch: one __syncthreads per K-chunk, L2 latency fully hidden.
__global__ void __launch_bounds__(128, 1) rec_kernel() {
    __shared__ float As[2][16][36];    // [buf][k][m]
    __shared__ float Bs[2][16][132];   // [buf][k][n]
    const int tid = threadIdx.x;
    const int blk = blockIdx.x;
    const int m0 = (blk >> 5) * 32;
    const int n0 = (blk & 31) * 128;
    const int ty = tid >> 5;           // 0..3  -> m sub-tile of 8
    const int tx = tid & 31;           // 0..31 -> n sub-tile of 4 (1 unit)
    const int am = tid >> 2;           // 0..31 A-loader row
    const int ak = (tid & 3) << 2;     // A-loader k-col
    const int br = tid >> 2;           // B-loader base row (rows br+32j)
    const int bkc = (tid & 3) << 2;    // B-loader k-col
    const int u = (n0 >> 2) + tx;      // hidden unit owned by this thread
    unsigned gen = 0;

#define STORE_A(buf, v)                                   \
    { As[buf][ak + 0][am] = (v).x; As[buf][ak + 1][am] = (v).y; \
      As[buf][ak + 2][am] = (v).z; As[buf][ak + 3][am] = (v).w; }
#define STORE_B(buf, v, j)                                       \
    { Bs[buf][bkc + 0][br + 32 * (j)] = (v).x; Bs[buf][bkc + 1][br + 32 * (j)] = (v).y; \
      Bs[buf][bkc + 2][br + 32 * (j)] = (v).z; Bs[buf][bkc + 3][br + 32 * (j)] = (v).w; }

    for (int t = 0; t < SS; t++) {
        const float* W = (t == 0) ? g_W0cat : g_Wcat;
        const float* arow = ((t == 0) ? (g_h0 + (size_t)(m0 + am) * HH)
                                      : (g_hist + ((size_t)(m0 + am) * SS + (t - 1)) * HH)) + ak;
        const float* brow = W + (size_t)(n0 + br) * HH + bkc;

        // prologue: chunk 0 -> buf0, preload chunk 1 into regs
        float4 aR = *(const float4*)arow;
        float4 bR0 = *(const float4*)(brow);
        float4 bR1 = *(const float4*)(brow + 32 * HH);
        float4 bR2 = *(const float4*)(brow + 64 * HH);
        float4 bR3 = *(const float4*)(brow + 96 * HH);
        STORE_A(0, aR);
        STORE_B(0, bR0, 0); STORE_B(0, bR1, 1); STORE_B(0, bR2, 2); STORE_B(0, bR3, 3);
        aR = *(const float4*)(arow + 16);
        bR0 = *(const float4*)(brow + 16);
        bR1 = *(const float4*)(brow + 32 * HH + 16);
        bR2 = *(const float4*)(brow + 64 * HH + 16);
        bR3 = *(const float4*)(brow + 96 * HH + 16);
        __syncthreads();

        unsigned long long acc[8][2];
#pragma unroll
        for (int i = 0; i < 8; i++) { acc[i][0] = 0ull; acc[i][1] = 0ull; }

        for (int c = 0; c < 64; c++) {
            const int cur = c & 1;
            if (c < 63) {
                STORE_A(cur ^ 1, aR);
                STORE_B(cur ^ 1, bR0, 0); STORE_B(cur ^ 1, bR1, 1);
                STORE_B(cur ^ 1, bR2, 2); STORE_B(cur ^ 1, bR3, 3);
            }
            if (c < 62) {
                const int off = (c + 2) * 16;
                aR = *(const float4*)(arow + off);
                bR0 = *(const float4*)(brow + off);
                bR1 = *(const float4*)(brow + 32 * HH + off);
                bR2 = *(const float4*)(brow + 64 * HH + off);
                bR3 = *(const float4*)(brow + 96 * HH + off);
            }
#pragma unroll
            for (int k = 0; k < 16; k++) {
                float4 a0 = *(const float4*)&As[cur][k][ty * 8];
                float4 a1 = *(const float4*)&As[cur][k][ty * 8 + 4];
                ulonglong2 bv = *(const ulonglong2*)&Bs[cur][k][tx * 4];
                unsigned long long p;
                p = pk2(a0.x); fma2(acc[0][0], p, bv.x); fma2(acc[0][1], p, bv.y);
                p = pk2(a0.y); fma2(acc[1][0], p, bv.x); fma2(acc[1][1], p, bv.y);
                p = pk2(a0.z); fma2(acc[2][0], p, bv.x); fma2(acc[2][1], p, bv.y);
                p = pk2(a0.w); fma2(acc[3][0], p, bv.x); fma2(acc[3][1], p, bv.y);
                p = pk2(a1.x); fma2(acc[4][0], p, bv.x); fma2(acc[4][1], p, bv.y);
                p = pk2(a1.y); fma2(acc[5][0], p, bv.x); fma2(acc[5][1], p, bv.y);
                p = pk2(a1.z); fma2(acc[6][0], p, bv.x); fma2(acc[6][1], p, bv.y);
                p = pk2(a1.w); fma2(acc[7][0], p, bv.x); fma2(acc[7][1], p, bv.y);
            }
            __syncthreads();
        }

        // gate fusion: thread owns unit u for 8 batch rows
        float4 bv4 = *(const float4*)&g_bc[u * 4];
#pragma unroll
        for (int i = 0; i < 8; i++) {
            const int b = m0 + ty * 8 + i;
            float pr, pz, pxn, phn;
            unp(acc[i][0], pr, pz);
            unp(acc[i][1], pxn, phn);
            float hp = (t == 0) ? g_h0[(size_t)b * HH + u]
                                : g_hist[((size_t)b * SS + (t - 1)) * HH + u];
            float r = 1.f / (1.f + expf(-(pr + bv4.x)));
            float z = 1.f / (1.f + expf(-(pz + bv4.y)));
            float nn = tanhf(pxn + bv4.z + r * (phn + bv4.w));
            g_hist[((size_t)b * SS + t) * HH + u] = (1.f - z) * nn + z * hp;
        }

        // grid barrier (128 co-resident blocks)
        __syncthreads();
        if (tid == 0) {
            gen++;
            __threadfence();
            unsigned prev = atomicAdd(&g_arr, 1u);
            if (prev == NBLK - 1) {
                g_arr = 0u;
                __threadfence();
                atomicExch(&g_rel, gen);
            } else {
                while (*(volatile unsigned*)&g_rel < gen) {}
                __threadfence();
            }
        }
        __syncthreads();
    }
#undef STORE_A
#undef STORE_B
}

// ---------------- batched attention + output -------------------------------------
// 1024 blocks = 128 b x 8 t-tiles(64). Online softmax over s (length-masked),
// accumulating only the 2 projected scalars per (b,t).
__global__ void __launch_bounds__(256) att_kernel(const float* __restrict__ enc,
                                                  const float* __restrict__ Wp,
                                                  const float* __restrict__ bp,
                                                  const int* __restrict__ lens,
                                                  float* __restrict__ out) {
    __shared__ float As[16][68];
    __shared__ float Bs[16][68];
    __shared__ float ec_s[64][2];
    const int bb = blockIdx.x >> 3;
    const int t0 = (blockIdx.x & 7) << 6;
    const int tid = threadIdx.x;
    const int ty = tid >> 4, tx = tid & 15;
    const int len = lens[bb];

    // hidden-state part of the projection: ph[j] = Wp[j,1024:] . h_t
    float ph0[4], ph1[4];
#pragma unroll
    for (int i = 0; i < 4; i++) {
        const int t = t0 + ty * 4 + i;
        const float* h = g_hist + ((size_t)bb * SS + t) * HH + tx * 64;
        float s0 = 0.f, s1 = 0.f;
#pragma unroll
        for (int c = 0; c < 16; c++) {
            float4 hv = *(const float4*)(h + c * 4);
            float4 w0 = *(const float4*)(Wp + 1024 + tx * 64 + c * 4);
            float4 w1 = *(const float4*)(Wp + 3072 + tx * 64 + c * 4);
            s0 += hv.x * w0.x + hv.y * w0.y + hv.z * w0.z + hv.w * w0.w;
            s1 += hv.x * w1.x + hv.y * w1.y + hv.z * w1.z + hv.w * w1.w;
        }
#pragma unroll
        for (int o = 8; o; o >>= 1) {
            s0 += __shfl_xor_sync(~0u, s0, o);
            s1 += __shfl_xor_sync(~0u, s1, o);
        }
        ph0[i] = s0; ph1[i] = s1;
    }

    float m[4], l[4], a0[4], a1[4];
#pragma unroll
    for (int i = 0; i < 4; i++) { m[i] = -1e30f; l[i] = 0.f; a0[i] = 0.f; a1[i] = 0.f; }

    const int am = tid >> 2, ak4 = (tid & 3) << 2;
    const float* hrow = g_hist + ((size_t)bb * SS + t0 + am) * HH + ak4;

    for (int sbase = 0; sbase < len; sbase += 64) {
        __syncthreads();
        if (tid < 64) {
            float2 e = *(const float2*)&g_ec[((size_t)bb * SS + sbase + tid) * 2];
            ec_s[tid][0] = e.x; ec_s[tid][1] = e.y;
        }
        const float* erow = enc + ((size_t)(sbase + am) * BB + bb) * HH + ak4;
        unsigned long long sc[4][2];
#pragma unroll
        for (int i = 0; i < 4; i++) { sc[i][0] = 0ull; sc[i][1] = 0ull; }

        for (int c = 0; c < 64; c++) {
            __syncthreads();
            float4 a4 = *(const float4*)(hrow + c * 16);
            As[ak4 + 0][am] = a4.x; As[ak4 + 1][am] = a4.y;
            As[ak4 + 2][am] = a4.z; As[ak4 + 3][am] = a4.w;
            float4 b4 = *(const float4*)(erow + c * 16);
            Bs[ak4 + 0][am] = b4.x; Bs[ak4 + 1][am] = b4.y;
            Bs[ak4 + 2][am] = b4.z; Bs[ak4 + 3][am] = b4.w;
            __syncthreads();
#pragma unroll
            for (int k = 0; k < 16; k++) {
                float4 av = *(const float4*)&As[k][ty * 4];
                ulonglong2 bpv = *(const ulonglong2*)&Bs[k][tx * 4];
                unsigned long long ax = pk2(av.x), ay = pk2(av.y);
                unsigned long long az = pk2(av.z), aw = pk2(av.w);
                fma2(sc[0][0], ax, bpv.x); fma2(sc[0][1], ax, bpv.y);
                fma2(sc[1][0], ay, bpv.x); fma2(sc[1][1], ay, bpv.y);
                fma2(sc[2][0], az, bpv.x); fma2(sc[2][1], az, bpv.y);
                fma2(sc[3][0], aw, bpv.x); fma2(sc[3][1], aw, bpv.y);
            }
        }

#pragma unroll
        for (int i = 0; i < 4; i++) {
            float s4[4];
            unp(sc[i][0], s4[0], s4[1]);
            unp(sc[i][1], s4[2], s4[3]);
#pragma unroll
            for (int j = 0; j < 4; j++)
                if (sbase + tx * 4 + j >= len) s4[j] = -1e30f;
            float cm = fmaxf(fmaxf(s4[0], s4[1]), fmaxf(s4[2], s4[3]));
#pragma unroll
            for (int o = 8; o; o >>= 1) cm = fmaxf(cm, __shfl_xor_sync(~0u, cm, o));
            const float mn = fmaxf(m[i], cm);
            const float alpha = __expf(m[i] - mn);
            float ws = 0.f, w0 = 0.f, w1 = 0.f;
#pragma unroll
            for (int j = 0; j < 4; j++) {
                float w = __expf(s4[j] - mn);
                ws += w;
                w0 += w * ec_s[tx * 4 + j][0];
                w1 += w * ec_s[tx * 4 + j][1];
            }
#pragma unroll
            for (int o = 8; o; o >>= 1) {
                ws += __shfl_xor_sync(~0u, ws, o);
                w0 += __shfl_xor_sync(~0u, w0, o);
                w1 += __shfl_xor_sync(~0u, w1, o);
            }
            l[i] = l[i] * alpha + ws;
            a0[i] = a0[i] * alpha + w0;
            a1[i] = a1[i] * alpha + w1;
            m[i] = mn;
        }
    }

    if (tx == 0) {
#pragma unroll
        for (int i = 0; i < 4; i++) {
            const int t = t0 + ty * 4 + i;
            const float inv = 1.f / l[i];
            out[((size_t)bb * SS + t) * 2 + 0] = a0[i] * inv + ph0[i] + bp[0];
            out[((size_t)bb * SS + t) * 2 + 1] = a1[i] * inv + ph1[i] + bp[1];
        }
    }
}

extern "C" void kernel_launch(void* const* d_in, const int* in_sizes, int n_in,
                              void* d_out, int out_size) {
    const float* enc  = (const float*)d_in[0];
    const float* last = (const float*)d_in[1];
    const float* Wih  = (const float*)d_in[2];
    const float* Whh  = (const float*)d_in[3];
    const float* bih  = (const float*)d_in[4];
    const float* bhh  = (const float*)d_in[5];
    const float* Wp   = (const float*)d_in[6];
    const float* bp   = (const float*)d_in[7];
    const int*   lens = (const int*)d_in[8];
    float* out = (float*)d_out;

    prep_kernel<<<4096, 256>>>(Wih, Whh, bih, bhh, last);
    ec_kernel<<<256, 256>>>(enc, Wp);
    rec_kernel<<<NBLK, 128>>>();
    att_kernel<<<1024, 256>>>(enc, Wp, bp, lens, out);
}